// round 4
// baseline (speedup 1.0000x reference)
#include <cuda_runtime.h>
#include <cuda_bf16.h>
#include <math.h>

// Problem constants (fixed by the reference setup_inputs)
#define NB 256   // batches
#define NA 64    // atoms
#define NE 128   // edges per batch
#define NK 6     // neighbors per edge
#define NH 256   // hidden
#define NH4 (NH / 4)          // 64 float4 per edge row
#define HSPLIT 8              // CTAs per batch along H
#define NH4S (NH4 / HSPLIT)   // 8 float4 per edge per CTA (128 B slice rows)
#define TILE (NE * NH4S)      // 1024 float4 outputs per CTA

__global__ __launch_bounds__(256)
void directed_edge_message_kernel(const float* __restrict__ rep,     // [1,B,E,H]
                                  const int*   __restrict__ pairs,   // [B,E,2]
                                  const int*   __restrict__ nbrs,    // [B,E,K]
                                  const float* __restrict__ xyz,     // [B,A,3]
                                  float*       __restrict__ out)     // [1,B,E,H]
{
    const int b   = blockIdx.x;
    const int hs  = blockIdx.y;            // 0..HSPLIT-1
    const int tid = threadIdx.x;

    __shared__ float dist_s[NE];
    __shared__ int   nb_s[NE * NK];

    // ---- Phase 1: per-edge inverse-squared-distance weight -----------------
    if (tid < NE) {
        const int base = (b * NE + tid) * 2;
        const int p0 = pairs[base + 0];
        const int p1 = pairs[base + 1];
        const float* x0 = xyz + ((size_t)b * NA + p0) * 3;
        const float* x1 = xyz + ((size_t)b * NA + p1) * 3;
        const float dx = x0[0] - x1[0];
        const float dy = x0[1] - x1[1];
        const float dz = x0[2] - x1[2];
        const float d2 = dx * dx + dy * dy + dz * dz;
        float inv = 1.0f / d2;
        // match jnp.where(isinf(inv), 0, inv)
        dist_s[tid] = isinf(inv) ? 0.0f : inv;
    }

    // Stage neighbor indices for this batch (E*K = 768 ints)
    #pragma unroll
    for (int i = tid; i < NE * NK; i += 256) {
        nb_s[i] = nbrs[(size_t)b * NE * NK + i];
    }
    __syncthreads();

    // ---- Phase 2: direct gather from global (L1-resident slice) ------------
    const float4* __restrict__ rep4 = reinterpret_cast<const float4*>(rep + (size_t)b * NE * NH);
    float4*       __restrict__ out4 = reinterpret_cast<float4*>(out + (size_t)b * NE * NH);
    const int hbase = hs * NH4S;

    // Per-CTA gather footprint: NE * NH4S * 16B = 16 KB -> stays hot in L1
    // across the 6x reuse with 8 CTAs/SM (128 KB << 228 KB L1).
    #pragma unroll
    for (int it = 0; it < TILE / 256; ++it) {
        const int i  = tid + it * 256;
        const int e  = i >> 3;            // / NH4S
        const int hl = i & (NH4S - 1);
        const int hc = hbase + hl;

        float4 acc = make_float4(0.f, 0.f, 0.f, 0.f);
        #pragma unroll
        for (int k = 0; k < NK; k++) {
            const int    nb = nb_s[e * NK + k];
            const float  w  = dist_s[nb];
            const float4 v  = rep4[nb * NH4 + hc];
            acc.x = fmaf(w, v.x, acc.x);
            acc.y = fmaf(w, v.y, acc.y);
            acc.z = fmaf(w, v.z, acc.z);
            acc.w = fmaf(w, v.w, acc.w);
        }
        out4[e * NH4 + hc] = acc;
    }
}

extern "C" void kernel_launch(void* const* d_in, const int* in_sizes, int n_in,
                              void* d_out, int out_size)
{
    const float* rep   = (const float*)d_in[0];  // bond_representations [1,B,E,H]
    const int*   pairs = (const int*)  d_in[1];  // bond_pairs          [B,E,2]
    const int*   nbrs  = (const int*)  d_in[2];  // bond_neighbors      [B,E,K]
    const float* xyz   = (const float*)d_in[3];  // xyz                 [B,A,3]
    float*       out   = (float*)d_out;          // [1,B,E,H]

    dim3 grid(NB, HSPLIT);
    directed_edge_message_kernel<<<grid, 256>>>(rep, pairs, nbrs, xyz, out);
}

// round 5
// speedup vs baseline: 1.0588x; 1.0588x over previous
#include <cuda_runtime.h>
#include <cuda_bf16.h>
#include <math.h>

// Problem constants (fixed by the reference setup_inputs)
#define NB 256   // batches
#define NA 64    // atoms
#define NE 128   // edges per batch
#define NK 6     // neighbors per edge
#define NH 256   // hidden
#define NH4 (NH / 4)          // 64 float4 per edge row
#define HSPLIT 8              // CTAs per batch along H
#define NH4S (NH4 / HSPLIT)   // 8 float4 per edge per CTA
#define TILE (NE * NH4S)      // 1024 float4 staged per CTA (16 KB)
#define ITER (TILE / 256)     // 4 outputs per thread

__global__ __launch_bounds__(256)
void directed_edge_message_kernel(const float* __restrict__ rep,     // [1,B,E,H]
                                  const int*   __restrict__ pairs,   // [B,E,2]
                                  const int*   __restrict__ nbrs,    // [B,E,K]
                                  const float* __restrict__ xyz,     // [B,A,3]
                                  float*       __restrict__ out)     // [1,B,E,H]
{
    const int b   = blockIdx.x;
    const int hs  = blockIdx.y;            // 0..HSPLIT-1
    const int tid = threadIdx.x;

    __shared__ float  dist_s[NE];
    __shared__ int    nb_s[NE * NK];
    __shared__ float4 ws4[TILE];           // UNWEIGHTED rep slice [E][NH4S]

    const float4* __restrict__ rep4 = reinterpret_cast<const float4*>(rep + (size_t)b * NE * NH);
    float4*       __restrict__ out4 = reinterpret_cast<float4*>(out + (size_t)b * NE * NH);
    const int hbase = hs * NH4S;

    // ---- Issue ALL independent global loads up front -----------------------
    // Stage tile: 4 float4 per thread (no dependency on dist -> full overlap)
    float4 stg[ITER];
    #pragma unroll
    for (int it = 0; it < ITER; ++it) {
        const int i = tid + it * 256;
        const int e  = i >> 3;            // / NH4S
        const int hl = i & (NH4S - 1);
        stg[it] = rep4[e * NH4 + hbase + hl];
    }
    // Neighbor indices: 3 ints per thread
    int nbv[3];
    #pragma unroll
    for (int j = 0; j < 3; ++j)
        nbv[j] = nbrs[(size_t)b * NE * NK + tid + j * 256];

    // ---- Phase 1: per-edge inverse-squared-distance (overlaps stage LDGs) --
    if (tid < NE) {
        const int base = (b * NE + tid) * 2;
        const int p0 = pairs[base + 0];
        const int p1 = pairs[base + 1];
        const float* x0 = xyz + ((size_t)b * NA + p0) * 3;
        const float* x1 = xyz + ((size_t)b * NA + p1) * 3;
        const float dx = x0[0] - x1[0];
        const float dy = x0[1] - x1[1];
        const float dz = x0[2] - x1[2];
        const float d2 = dx * dx + dy * dy + dz * dz;
        float inv = 1.0f / d2;
        // match jnp.where(isinf(inv), 0, inv)
        dist_s[tid] = isinf(inv) ? 0.0f : inv;
    }

    // ---- Stores to SMEM, then a SINGLE barrier ------------------------------
    #pragma unroll
    for (int it = 0; it < ITER; ++it)
        ws4[tid + it * 256] = stg[it];
    #pragma unroll
    for (int j = 0; j < 3; ++j)
        nb_s[tid + j * 256] = nbv[j];

    __syncthreads();

    // ---- Gather from SMEM, weight on consume, write out --------------------
    #pragma unroll
    for (int it = 0; it < ITER; ++it) {
        const int i  = tid + it * 256;
        const int e  = i >> 3;
        const int hl = i & (NH4S - 1);

        float4 acc = make_float4(0.f, 0.f, 0.f, 0.f);
        #pragma unroll
        for (int k = 0; k < NK; k++) {
            const int    nb = nb_s[e * NK + k];
            const float  w  = dist_s[nb];            // broadcast LDS
            const float4 v  = ws4[nb * NH4S + hl];   // conflict-free 128B row
            acc.x = fmaf(w, v.x, acc.x);
            acc.y = fmaf(w, v.y, acc.y);
            acc.z = fmaf(w, v.z, acc.z);
            acc.w = fmaf(w, v.w, acc.w);
        }
        out4[e * NH4 + hbase + hl] = acc;
    }
}

extern "C" void kernel_launch(void* const* d_in, const int* in_sizes, int n_in,
                              void* d_out, int out_size)
{
    const float* rep   = (const float*)d_in[0];  // bond_representations [1,B,E,H]
    const int*   pairs = (const int*)  d_in[1];  // bond_pairs          [B,E,2]
    const int*   nbrs  = (const int*)  d_in[2];  // bond_neighbors      [B,E,K]
    const float* xyz   = (const float*)d_in[3];  // xyz                 [B,A,3]
    float*       out   = (float*)d_out;          // [1,B,E,H]

    dim3 grid(NB, HSPLIT);
    directed_edge_message_kernel<<<grid, 256>>>(rep, pairs, nbrs, xyz, out);
}